// round 1
// baseline (speedup 1.0000x reference)
#include <cuda_runtime.h>
#include <cstdint>

#define NMAX 100000
#define EMAX 1600000
#define HID 128
#define GNUM 64
#define RELN 51
#define NEG 0.2f
#define RB 512  // BN reduce stage-1 blocks

// ---------------- scratch (module-static, allowed) ----------------
__device__ float g_x0[(size_t)NMAX * 288];
__device__ float g_h[(size_t)NMAX * HID];
__device__ float g_xl[(size_t)NMAX * HID];
__device__ float g_xr[(size_t)NMAX * HID];
__device__ float g_agg[(size_t)NMAX * HID];
__device__ float g_eetab[RELN * HID];
__device__ float g_part[RB * HID];
__device__ float g_part2[RB * HID];
__device__ float g_scale[HID];
__device__ float g_shift[HID];
__device__ float g_pool[GNUM * HID];
__device__ int   g_pcnt[GNUM];
__device__ int   g_deg[NMAX];
__device__ int   g_rowptr[NMAX + 1];
__device__ int   g_scan[NMAX];
__device__ int   g_bsum[128];
__device__ int   g_csr[EMAX];

// ---------------- f32x2 helpers (packed fp32, 2x FFMA rate) ----------------
__device__ __forceinline__ unsigned long long pack2(float lo, float hi) {
    unsigned long long r;
    asm("mov.b64 %0, {%1,%2};" : "=l"(r) : "f"(lo), "f"(hi));
    return r;
}
__device__ __forceinline__ unsigned long long fma2(unsigned long long a,
                                                   unsigned long long b,
                                                   unsigned long long c) {
    unsigned long long d;
    asm("fma.rn.f32x2 %0, %1, %2, %3;" : "=l"(d) : "l"(a), "l"(b), "l"(c));
    return d;
}
__device__ __forceinline__ float2 unpack2(unsigned long long v) {
    float2 f;
    asm("mov.b64 {%0,%1}, %2;" : "=f"(f.x), "=f"(f.y) : "l"(v));
    return f;
}

// ---------------- input feature build ----------------
__global__ void k_build_x0(const int* __restrict__ tok,
                           const float* __restrict__ bbox,
                           const float* __restrict__ temb,
                           const float* __restrict__ bW,
                           const float* __restrict__ bb, int n) {
    int idx = blockIdx.x * blockDim.x + threadIdx.x;
    int total = n * 288;
    if (idx >= total) return;
    int node = idx / 288;
    int c = idx - node * 288;
    float v;
    if (c < 256) {
        v = temb[tok[node] * 256 + c];
    } else {
        int j = c - 256;
        float s = bb[j];
#pragma unroll
        for (int i = 0; i < 4; i++) s += bbox[node * 4 + i] * bW[i * 32 + j];
        v = s;
    }
    g_x0[idx] = v;
}

// ---------------- edge-embedding table (rel_emb @ We) ----------------
__global__ void k_eetab(const float* __restrict__ relemb,
                        const float* __restrict__ We) {
    int idx = blockIdx.x * blockDim.x + threadIdx.x;
    if (idx >= RELN * HID) return;
    int r = idx >> 7, j = idx & 127;
    float s = 0.f;
#pragma unroll
    for (int c = 0; c < 16; c++) s += relemb[r * 16 + c] * We[c * 128 + j];
    g_eetab[idx] = s;
}

// ---------------- CSR build ----------------
__global__ void k_zero_deg(int n) {
    int i = blockIdx.x * blockDim.x + threadIdx.x;
    if (i < n) g_deg[i] = 0;
}
__global__ void k_hist(const int* __restrict__ dst, int e) {
    int i = blockIdx.x * blockDim.x + threadIdx.x;
    if (i < e) atomicAdd(&g_deg[dst[i]], 1);
}
__global__ void k_scan1(int n) {
    __shared__ int sh[1024];
    int t = threadIdx.x;
    int i = blockIdx.x * 1024 + t;
    int v = (i < n) ? g_deg[i] : 0;
    sh[t] = v;
    __syncthreads();
    for (int off = 1; off < 1024; off <<= 1) {
        int x = (t >= off) ? sh[t - off] : 0;
        __syncthreads();
        sh[t] += x;
        __syncthreads();
    }
    if (i < n) g_scan[i] = sh[t];
    if (t == 1023) g_bsum[blockIdx.x] = sh[1023];
}
__global__ void k_scan2(int nb) {
    if (threadIdx.x == 0 && blockIdx.x == 0) {
        int s = 0;
        for (int b = 0; b < nb; b++) { s += g_bsum[b]; g_bsum[b] = s; }
    }
}
__global__ void k_scan3(int n) {
    int i = blockIdx.x * blockDim.x + threadIdx.x;
    if (i >= n) return;
    int b = i >> 10;
    int off = b ? g_bsum[b - 1] : 0;
    g_rowptr[i + 1] = g_scan[i] + off;
    if (i == 0) g_rowptr[0] = 0;
}
__global__ void k_scatter(const int* __restrict__ src,
                          const int* __restrict__ dst,
                          const int* __restrict__ rel, int e) {
    int i = blockIdx.x * blockDim.x + threadIdx.x;
    if (i >= e) return;
    int d = dst[i];
    int pos = g_rowptr[d] + atomicAdd(&g_deg[d], 1);
    g_csr[pos] = src[i] | (rel[i] << 20);
}

// ---------------- GEMM: Y[n,128] = X[n,IND] @ W[IND,128] + B ----------------
// block 256 thr, tile 32 rows x 128 cols; thread = 4 rows x 4 cols, f32x2 packed.
template <int IND>
__global__ void __launch_bounds__(256) k_gemm(const float* __restrict__ X,
                                              const float* __restrict__ W,
                                              const float* __restrict__ B,
                                              float* __restrict__ Y, int n) {
    __shared__ float ws[32][128];
    __shared__ float xs[32][36];
    int t = threadIdx.x;
    int cg = t & 31, ng = t >> 5;
    int nb = blockIdx.x * 32;

    float4 b4 = *(const float4*)&B[cg * 4];
    unsigned long long acc[4][2];
    acc[0][0] = acc[0][1] = pack2(b4.x, b4.x);
    acc[1][0] = acc[1][1] = pack2(b4.y, b4.y);
    acc[2][0] = acc[2][1] = pack2(b4.z, b4.z);
    acc[3][0] = acc[3][1] = pack2(b4.w, b4.w);

    for (int kt = 0; kt < IND; kt += 32) {
        {   // stage x tile transposed
            int nn = t >> 3, kk = (t & 7) * 4;
            int row = nb + nn;
            float4 xv = make_float4(0.f, 0.f, 0.f, 0.f);
            if (row < n) xv = *(const float4*)&X[(size_t)row * IND + kt + kk];
            xs[kk + 0][nn] = xv.x;
            xs[kk + 1][nn] = xv.y;
            xs[kk + 2][nn] = xv.z;
            xs[kk + 3][nn] = xv.w;
            // stage W tile
#pragma unroll
            for (int j = 0; j < 4; j++) {
                int u = t + j * 256;
                int r = u >> 5, c4 = (u & 31) * 4;
                *(float4*)&ws[r][c4] = *(const float4*)&W[(size_t)(kt + r) * 128 + c4];
            }
        }
        __syncthreads();
#pragma unroll
        for (int k = 0; k < 32; k++) {
            float4 w4 = *(const float4*)&ws[k][cg * 4];
            ulonglong2 xp = *(const ulonglong2*)&xs[k][ng * 4];
            unsigned long long wd;
            wd = pack2(w4.x, w4.x);
            acc[0][0] = fma2(wd, xp.x, acc[0][0]);
            acc[0][1] = fma2(wd, xp.y, acc[0][1]);
            wd = pack2(w4.y, w4.y);
            acc[1][0] = fma2(wd, xp.x, acc[1][0]);
            acc[1][1] = fma2(wd, xp.y, acc[1][1]);
            wd = pack2(w4.z, w4.z);
            acc[2][0] = fma2(wd, xp.x, acc[2][0]);
            acc[2][1] = fma2(wd, xp.y, acc[2][1]);
            wd = pack2(w4.w, w4.w);
            acc[3][0] = fma2(wd, xp.x, acc[3][0]);
            acc[3][1] = fma2(wd, xp.y, acc[3][1]);
        }
        __syncthreads();
    }
    float2 q[4][2];
#pragma unroll
    for (int c = 0; c < 4; c++) {
        q[c][0] = unpack2(acc[c][0]);
        q[c][1] = unpack2(acc[c][1]);
    }
    int base = nb + ng * 4;
    if (base + 0 < n) {
        float4 r = {q[0][0].x, q[1][0].x, q[2][0].x, q[3][0].x};
        *(float4*)&Y[(size_t)(base + 0) * 128 + cg * 4] = r;
    }
    if (base + 1 < n) {
        float4 r = {q[0][0].y, q[1][0].y, q[2][0].y, q[3][0].y};
        *(float4*)&Y[(size_t)(base + 1) * 128 + cg * 4] = r;
    }
    if (base + 2 < n) {
        float4 r = {q[0][1].x, q[1][1].x, q[2][1].x, q[3][1].x};
        *(float4*)&Y[(size_t)(base + 2) * 128 + cg * 4] = r;
    }
    if (base + 3 < n) {
        float4 r = {q[0][1].y, q[1][1].y, q[2][1].y, q[3][1].y};
        *(float4*)&Y[(size_t)(base + 3) * 128 + cg * 4] = r;
    }
}

// ---------------- fused edge pass: per dst node, online softmax ----------------
__global__ void __launch_bounds__(256) k_edge(const float* __restrict__ att, int n) {
    __shared__ float ee[RELN * HID];
    int t = threadIdx.x;
    for (int i = t; i < RELN * HID; i += 256) ee[i] = g_eetab[i];
    __syncthreads();
    int lane = t & 31, wid = t >> 5;
    int hd = lane >> 2;
    float4 av = *(const float4*)&att[hd * 16 + (lane & 3) * 4];
    int wtot = gridDim.x * 8;
    for (int node = blockIdx.x * 8 + wid; node < n; node += wtot) {
        int r0 = g_rowptr[node], r1 = g_rowptr[node + 1];
        float4 xr = *(const float4*)&g_xr[(size_t)node * 128 + lane * 4];
        float4 acc = {0.f, 0.f, 0.f, 0.f};
        float den = 0.f, mx = -3.0e38f;
        for (int i = r0; i < r1; i++) {
            int pe = g_csr[i];
            int src = pe & 0xFFFFF, rel = pe >> 20;
            float4 xl = *(const float4*)&g_xl[(size_t)src * 128 + lane * 4];
            float4 ev = *(const float4*)&ee[rel * 128 + lane * 4];
            float m0 = xl.x + xr.x + ev.x; m0 = m0 > 0.f ? m0 : NEG * m0;
            float m1 = xl.y + xr.y + ev.y; m1 = m1 > 0.f ? m1 : NEG * m1;
            float m2 = xl.z + xr.z + ev.z; m2 = m2 > 0.f ? m2 : NEG * m2;
            float m3 = xl.w + xr.w + ev.w; m3 = m3 > 0.f ? m3 : NEG * m3;
            float s = m0 * av.x + m1 * av.y + m2 * av.z + m3 * av.w;
            s += __shfl_xor_sync(0xffffffffu, s, 1);
            s += __shfl_xor_sync(0xffffffffu, s, 2);
            float nm = fmaxf(mx, s);
            float fac = __expf(mx - nm);
            float p = __expf(s - nm);
            den = den * fac + p;
            acc.x = acc.x * fac + p * xl.x;
            acc.y = acc.y * fac + p * xl.y;
            acc.z = acc.z * fac + p * xl.z;
            acc.w = acc.w * fac + p * xl.w;
            mx = nm;
        }
        float inv = 1.0f / fmaxf(den, 1e-16f);
        float4 o = {acc.x * inv, acc.y * inv, acc.z * inv, acc.w * inv};
        *(float4*)&g_agg[(size_t)node * 128 + lane * 4] = o;
    }
}

// ---------------- batch norm (deterministic two-stage) + apply ----------------
__global__ void k_bnr1(const float* __restrict__ bias, int n) {
    int c = threadIdx.x;
    int b = blockIdx.x;
    float bc = bias[c];
    float s = 0.f, q = 0.f;
    for (int r = b; r < n; r += gridDim.x) {
        float v = g_agg[(size_t)r * 128 + c] + bc;
        v = v > 0.f ? v : 0.f;
        s += v;
        q += v * v;
    }
    g_part[b * 128 + c] = s;
    g_part2[b * 128 + c] = q;
}
__global__ void k_bnr2(const float* __restrict__ gamma,
                       const float* __restrict__ beta, int n) {
    int c = threadIdx.x;
    float s = 0.f, q = 0.f;
    for (int b = 0; b < RB; b++) {
        s += g_part[b * 128 + c];
        q += g_part2[b * 128 + c];
    }
    float inv_n = 1.0f / (float)n;
    float mu = s * inv_n;
    float var = q * inv_n - mu * mu;
    float rs = rsqrtf(var + 1e-5f);
    float sc = gamma[c] * rs;
    g_scale[c] = sc;
    g_shift[c] = beta[c] - mu * sc;
}
__global__ void k_apply(const float* __restrict__ bias, int res, int n) {
    int idx = blockIdx.x * blockDim.x + threadIdx.x;
    if (idx >= n * 128) return;
    int c = idx & 127;
    float v = g_agg[idx] + bias[c];
    v = v > 0.f ? v : 0.f;
    float o = g_scale[c] * v + g_shift[c];
    g_h[idx] = res ? (g_h[idx] + o) : o;
}

// ---------------- pooling ----------------
__global__ void k_pool_zero() {
    int i = blockIdx.x * blockDim.x + threadIdx.x;
    if (i < GNUM * HID) g_pool[i] = 0.f;
    if (i < GNUM) g_pcnt[i] = 0;
}
__global__ void k_pool(const int* __restrict__ batch, int n) {
    const int CHUNK = 256;
    int t = threadIdx.x;  // channel
    int r0 = blockIdx.x * CHUNK;
    int rend = min(r0 + CHUNK, n);
    float a = 0.f;
    int lc = 0, cur = -1;
    for (int r = r0; r < rend; r++) {
        int g = batch[r];
        if (g != cur) {
            if (cur >= 0) {
                atomicAdd(&g_pool[cur * 128 + t], a);
                if (t == 0) atomicAdd(&g_pcnt[cur], lc);
            }
            a = 0.f;
            lc = 0;
            cur = g;
        }
        a += g_h[(size_t)r * 128 + t];
        lc++;
    }
    if (cur >= 0) {
        atomicAdd(&g_pool[cur * 128 + t], a);
        if (t == 0) atomicAdd(&g_pcnt[cur], lc);
    }
}
__global__ void k_pool_fin(float* __restrict__ out) {
    int i = blockIdx.x * blockDim.x + threadIdx.x;
    if (i >= GNUM * HID) return;
    out[i] = g_pool[i] / fmaxf((float)g_pcnt[i >> 7], 1.0f);
}

// ---------------- host launch ----------------
extern "C" void kernel_launch(void* const* d_in, const int* in_sizes, int n_in,
                              void* d_out, int out_size) {
    const int* tok = (const int*)d_in[0];
    const float* bbox = (const float*)d_in[1];
    const int* ei = (const int*)d_in[2];
    const int* eattr = (const int*)d_in[3];
    const int* batch = (const int*)d_in[4];
    const float* temb = (const float*)d_in[5];
    const float* bW = (const float*)d_in[6];
    const float* bb = (const float*)d_in[7];
    const float* relemb = (const float*)d_in[8];
    const float* Wl0 = (const float*)d_in[9];
    const float* bl0 = (const float*)d_in[10];
    const float* Wr0 = (const float*)d_in[11];
    const float* br0 = (const float*)d_in[12];
    const float* We0 = (const float*)d_in[13];
    const float* att0 = (const float*)d_in[14];
    const float* bias0 = (const float*)d_in[15];
    const float* gamma0 = (const float*)d_in[16];
    const float* beta0 = (const float*)d_in[17];
    const float* WlS = (const float*)d_in[18];
    const float* blS = (const float*)d_in[19];
    const float* WrS = (const float*)d_in[20];
    const float* brS = (const float*)d_in[21];
    const float* WeS = (const float*)d_in[22];
    const float* attS = (const float*)d_in[23];
    const float* biasS = (const float*)d_in[24];
    const float* gammaS = (const float*)d_in[25];
    const float* betaS = (const float*)d_in[26];

    int n = in_sizes[0];
    int e = in_sizes[3];
    const int* src = ei;
    const int* dst = ei + e;

    float *p_x0, *p_h, *p_xl, *p_xr;
    cudaGetSymbolAddress((void**)&p_x0, g_x0);
    cudaGetSymbolAddress((void**)&p_h, g_h);
    cudaGetSymbolAddress((void**)&p_xl, g_xl);
    cudaGetSymbolAddress((void**)&p_xr, g_xr);

    int gN = (n + 255) / 256;
    int gE = (e + 255) / 256;

    // feature build
    k_build_x0<<<(n * 288 + 255) / 256, 256>>>(tok, bbox, temb, bW, bb, n);

    // CSR build
    int nbScan = (n + 1023) / 1024;
    k_zero_deg<<<gN, 256>>>(n);
    k_hist<<<gE, 256>>>(dst, e);
    k_scan1<<<nbScan, 1024>>>(n);
    k_scan2<<<1, 32>>>(nbScan);
    k_scan3<<<gN, 256>>>(n);
    k_zero_deg<<<gN, 256>>>(n);
    k_scatter<<<gE, 256>>>(src, dst, eattr, e);

    int gemmGrid = (n + 31) / 32;
    int edgeGrid = (n + 63) / 64;

    for (int l = 0; l < 3; l++) {
        const float *Wl, *bl, *Wr, *br, *We, *att, *bias, *gamma, *beta;
        if (l == 0) {
            Wl = Wl0; bl = bl0; Wr = Wr0; br = br0; We = We0;
            att = att0; bias = bias0; gamma = gamma0; beta = beta0;
        } else {
            int j = l - 1;
            Wl = WlS + (size_t)j * 128 * 128; bl = blS + j * 128;
            Wr = WrS + (size_t)j * 128 * 128; br = brS + j * 128;
            We = WeS + (size_t)j * 16 * 128;
            att = attS + j * 128;
            bias = biasS + j * 128; gamma = gammaS + j * 128; beta = betaS + j * 128;
        }
        k_eetab<<<(RELN * HID + 255) / 256, 256>>>(relemb, We);
        if (l == 0) {
            k_gemm<288><<<gemmGrid, 256>>>(p_x0, Wl, bl, p_xl, n);
            k_gemm<288><<<gemmGrid, 256>>>(p_x0, Wr, br, p_xr, n);
        } else {
            k_gemm<128><<<gemmGrid, 256>>>(p_h, Wl, bl, p_xl, n);
            k_gemm<128><<<gemmGrid, 256>>>(p_h, Wr, br, p_xr, n);
        }
        k_edge<<<edgeGrid, 256>>>(att, n);
        k_bnr1<<<RB, 128>>>(bias, n);
        k_bnr2<<<1, 128>>>(gamma, beta, n);
        k_apply<<<(n * 128 + 255) / 256, 256>>>(bias, l > 0 ? 1 : 0, n);
    }

    // pooling
    k_pool_zero<<<(GNUM * HID + 255) / 256, 256>>>();
    k_pool<<<(n + 255) / 256, 128>>>(batch, n);
    k_pool_fin<<<(GNUM * HID + 255) / 256, 256>>>((float*)d_out);
}

// round 2
// speedup vs baseline: 1.2465x; 1.2465x over previous
#include <cuda_runtime.h>
#include <cstdint>

#define NMAX 100000
#define EMAX 1600000
#define HID 128
#define GNUM 64
#define RELN 51
#define NEG 0.2f
#define EG 592   // edge-pass grid (4 * 148)

// ---------------- scratch ----------------
__device__ float g_x0[(size_t)NMAX * 288];
__device__ float g_h[(size_t)NMAX * HID];
__device__ float g_xl[(size_t)NMAX * HID];
__device__ float g_xr[(size_t)NMAX * HID];
__device__ float g_agg[(size_t)NMAX * HID];
__device__ float g_eetab[RELN * HID];
__device__ float g_part[EG * 256];
__device__ float g_scale[HID];
__device__ float g_shift[HID];
__device__ float g_pool[GNUM * HID];
__device__ int   g_pcnt[GNUM];
__device__ int   g_deg[NMAX];
__device__ int   g_rowptr[NMAX + 1];
__device__ int   g_scan[NMAX];
__device__ int   g_bsum[128];
__device__ int   g_csr[EMAX];

// ---------------- f32x2 helpers ----------------
__device__ __forceinline__ unsigned long long pack2(float lo, float hi) {
    unsigned long long r;
    asm("mov.b64 %0, {%1,%2};" : "=l"(r) : "f"(lo), "f"(hi));
    return r;
}
__device__ __forceinline__ unsigned long long fma2(unsigned long long a,
                                                   unsigned long long b,
                                                   unsigned long long c) {
    unsigned long long d;
    asm("fma.rn.f32x2 %0, %1, %2, %3;" : "=l"(d) : "l"(a), "l"(b), "l"(c));
    return d;
}
__device__ __forceinline__ float2 unpack2(unsigned long long v) {
    float2 f;
    asm("mov.b64 {%0,%1}, %2;" : "=f"(f.x), "=f"(f.y) : "l"(v));
    return f;
}

// ---------------- input feature build (float4) ----------------
__global__ void k_build_x0(const int* __restrict__ tok,
                           const float* __restrict__ bbox,
                           const float* __restrict__ temb,
                           const float* __restrict__ bW,
                           const float* __restrict__ bb, int n) {
    int idx = blockIdx.x * blockDim.x + threadIdx.x;
    if (idx >= n * 72) return;
    int node = idx / 72;
    int c4 = (idx - node * 72) * 4;
    float4 v;
    if (c4 < 256) {
        v = *(const float4*)&temb[(size_t)tok[node] * 256 + c4];
    } else {
        int j = c4 - 256;
        float4 b0 = *(const float4*)&bbox[node * 4];
        v.x = bb[j];     v.y = bb[j + 1]; v.z = bb[j + 2]; v.w = bb[j + 3];
        const float* bw0 = &bW[j];
        v.x += b0.x * bw0[0]   + b0.y * bw0[32]   + b0.z * bw0[64]   + b0.w * bw0[96];
        v.y += b0.x * bw0[1]   + b0.y * bw0[33]   + b0.z * bw0[65]   + b0.w * bw0[97];
        v.z += b0.x * bw0[2]   + b0.y * bw0[34]   + b0.z * bw0[66]   + b0.w * bw0[98];
        v.w += b0.x * bw0[3]   + b0.y * bw0[35]   + b0.z * bw0[67]   + b0.w * bw0[99];
    }
    *(float4*)&g_x0[(size_t)node * 288 + c4] = v;
}

// ---------------- edge-embedding table ----------------
__global__ void k_eetab(const float* __restrict__ relemb,
                        const float* __restrict__ We) {
    int idx = blockIdx.x * blockDim.x + threadIdx.x;
    if (idx >= RELN * HID) return;
    int r = idx >> 7, j = idx & 127;
    float s = 0.f;
#pragma unroll
    for (int c = 0; c < 16; c++) s += relemb[r * 16 + c] * We[c * 128 + j];
    g_eetab[idx] = s;
}

// ---------------- CSR build ----------------
__global__ void k_zero_deg(int n) {
    int i = blockIdx.x * blockDim.x + threadIdx.x;
    if (i < n) g_deg[i] = 0;
}
__global__ void k_hist(const int* __restrict__ dst, int e) {
    int i = blockIdx.x * blockDim.x + threadIdx.x;
    if (i < e) atomicAdd(&g_deg[dst[i]], 1);
}
__global__ void k_scan1(int n) {
    __shared__ int sh[1024];
    int t = threadIdx.x;
    int i = blockIdx.x * 1024 + t;
    int v = (i < n) ? g_deg[i] : 0;
    sh[t] = v;
    __syncthreads();
    for (int off = 1; off < 1024; off <<= 1) {
        int x = (t >= off) ? sh[t - off] : 0;
        __syncthreads();
        sh[t] += x;
        __syncthreads();
    }
    if (i < n) g_scan[i] = sh[t];
    if (t == 1023) g_bsum[blockIdx.x] = sh[1023];
}
__global__ void k_scan2(int nb) {
    if (threadIdx.x == 0 && blockIdx.x == 0) {
        int s = 0;
        for (int b = 0; b < nb; b++) { s += g_bsum[b]; g_bsum[b] = s; }
    }
}
__global__ void k_scan3(int n) {
    int i = blockIdx.x * blockDim.x + threadIdx.x;
    if (i >= n) return;
    int b = i >> 10;
    int off = b ? g_bsum[b - 1] : 0;
    g_rowptr[i + 1] = g_scan[i] + off;
    if (i == 0) g_rowptr[0] = 0;
}
__global__ void k_scatter(const int* __restrict__ src,
                          const int* __restrict__ dst,
                          const int* __restrict__ rel, int e) {
    int i = blockIdx.x * blockDim.x + threadIdx.x;
    if (i >= e) return;
    int d = dst[i];
    int pos = g_rowptr[d] + atomicAdd(&g_deg[d], 1);
    g_csr[pos] = src[i] | (rel[i] << 20);
}

// ---------------- fused dual GEMM: Yl/Yr = X @ Wl/Wr + bl/br ----------------
// block 256, tile 64 rows x (128+128) cols; thread = 8 rows x 8 cols (f32x2).
// W staged in smem pre-duplicated as (w,w) ulonglong pairs -> no per-k packs.
template <int IND>
__global__ void __launch_bounds__(256, 2)
k_gemm2(const float* __restrict__ X,
        const float* __restrict__ Wl, const float* __restrict__ bl,
        const float* __restrict__ Wr, const float* __restrict__ br,
        float* __restrict__ Yl, float* __restrict__ Yr, int n) {
    const int KT = 16;
    __shared__ ulonglong2 ws2[KT][128];   // col pairs, duplicated
    __shared__ float xs[KT][72];          // transposed X tile
    int t = threadIdx.x;
    int cg = t & 31;   // lane -> owns cols {2cg, 2cg+1} in 4 blocks of 64
    int ng = t >> 5;   // warp -> rows ng*8 .. ng*8+7
    int rowbase = blockIdx.x * 64;

    // bias init
    unsigned long long acc[4][2][4];
#pragma unroll
    for (int g = 0; g < 4; g++) {
        int col = g * 64 + 2 * cg;
        float2 bv = (g < 2) ? *(const float2*)&bl[col]
                            : *(const float2*)&br[col - 128];
        unsigned long long p0 = pack2(bv.x, bv.x);
        unsigned long long p1 = pack2(bv.y, bv.y);
#pragma unroll
        for (int rp = 0; rp < 4; rp++) { acc[g][0][rp] = p0; acc[g][1][rp] = p1; }
    }

    for (int kt = 0; kt < IND; kt += KT) {
        // stage X tile (transposed): thread -> row t>>2, k-quad (t&3)*4
        {
            int rr = t >> 2, kk = (t & 3) * 4;
            int grow = rowbase + rr;
            float4 xv = make_float4(0.f, 0.f, 0.f, 0.f);
            if (grow < n) xv = *(const float4*)&X[(size_t)grow * IND + kt + kk];
            xs[kk + 0][rr] = xv.x;
            xs[kk + 1][rr] = xv.y;
            xs[kk + 2][rr] = xv.z;
            xs[kk + 3][rr] = xv.w;
        }
        // stage W tile duplicated: 2048 col-pair chunks
#pragma unroll
        for (int j = 0; j < 8; j++) {
            int id = j * 256 + t;
            int krow = id >> 7, c2 = id & 127;
            int col = c2 * 2;
            float2 wv;
            if (col < 128) wv = *(const float2*)&Wl[(size_t)(kt + krow) * 128 + col];
            else           wv = *(const float2*)&Wr[(size_t)(kt + krow) * 128 + (col - 128)];
            ulonglong2 d;
            d.x = pack2(wv.x, wv.x);
            d.y = pack2(wv.y, wv.y);
            ws2[krow][c2] = d;
        }
        __syncthreads();
#pragma unroll
        for (int k = 0; k < KT; k++) {
            ulonglong2 xa = *(const ulonglong2*)&xs[k][ng * 8];
            ulonglong2 xb = *(const ulonglong2*)&xs[k][ng * 8 + 4];
            unsigned long long xp0 = xa.x, xp1 = xa.y, xp2 = xb.x, xp3 = xb.y;
#pragma unroll
            for (int g = 0; g < 4; g++) {
                ulonglong2 w2 = ws2[k][g * 32 + cg];
                acc[g][0][0] = fma2(w2.x, xp0, acc[g][0][0]);
                acc[g][0][1] = fma2(w2.x, xp1, acc[g][0][1]);
                acc[g][0][2] = fma2(w2.x, xp2, acc[g][0][2]);
                acc[g][0][3] = fma2(w2.x, xp3, acc[g][0][3]);
                acc[g][1][0] = fma2(w2.y, xp0, acc[g][1][0]);
                acc[g][1][1] = fma2(w2.y, xp1, acc[g][1][1]);
                acc[g][1][2] = fma2(w2.y, xp2, acc[g][1][2]);
                acc[g][1][3] = fma2(w2.y, xp3, acc[g][1][3]);
            }
        }
        __syncthreads();
    }
    // epilogue: each acc[g][c][rp] holds rows (2rp, 2rp+1) of col g*64+2cg+c
#pragma unroll
    for (int rp = 0; rp < 4; rp++) {
        int r = rowbase + ng * 8 + rp * 2;
#pragma unroll
        for (int g = 0; g < 4; g++) {
            float2 v0 = unpack2(acc[g][0][rp]);
            float2 v1 = unpack2(acc[g][1][rp]);
            int colL = (g & 1) * 64 + 2 * cg;
            float* Y = (g < 2) ? Yl : Yr;
            if (r < n)     *(float2*)&Y[(size_t)r * 128 + colL] = make_float2(v0.x, v1.x);
            if (r + 1 < n) *(float2*)&Y[(size_t)(r + 1) * 128 + colL] = make_float2(v0.y, v1.y);
        }
    }
}

// ---------------- fused edge pass + bias + relu + BN partials ----------------
__global__ void __launch_bounds__(256) k_edge(const float* __restrict__ att,
                                              const float* __restrict__ bias, int n) {
    __shared__ float ee[RELN * HID];
    __shared__ float red[8][32][8];
    int t = threadIdx.x;
    for (int i = t; i < RELN * HID; i += 256) ee[i] = g_eetab[i];
    __syncthreads();
    int lane = t & 31, wid = t >> 5;
    float4 av = *(const float4*)&att[(lane >> 2) * 16 + (lane & 3) * 4];
    float4 bv = *(const float4*)&bias[lane * 4];
    float ps0 = 0.f, ps1 = 0.f, ps2 = 0.f, ps3 = 0.f;
    float pq0 = 0.f, pq1 = 0.f, pq2 = 0.f, pq3 = 0.f;

    for (int node = blockIdx.x * 8 + wid; node < n; node += EG * 8) {
        int r0 = g_rowptr[node], r1 = g_rowptr[node + 1];
        float4 xr = *(const float4*)&g_xr[(size_t)node * 128 + lane * 4];
        float4 acc = {0.f, 0.f, 0.f, 0.f};
        float den = 0.f;
        int i = r0;
        for (; i + 2 <= r1; i += 2) {
            int pe0 = g_csr[i], pe1 = g_csr[i + 1];
            float4 xl0 = *(const float4*)&g_xl[(size_t)(pe0 & 0xFFFFF) * 128 + lane * 4];
            float4 ev0 = *(const float4*)&ee[(pe0 >> 20) * 128 + lane * 4];
            float4 xl1 = *(const float4*)&g_xl[(size_t)(pe1 & 0xFFFFF) * 128 + lane * 4];
            float4 ev1 = *(const float4*)&ee[(pe1 >> 20) * 128 + lane * 4];
            float m, s0, s1;
            m = xl0.x + xr.x + ev0.x; m = m > 0.f ? m : NEG * m; s0 = m * av.x;
            m = xl0.y + xr.y + ev0.y; m = m > 0.f ? m : NEG * m; s0 += m * av.y;
            m = xl0.z + xr.z + ev0.z; m = m > 0.f ? m : NEG * m; s0 += m * av.z;
            m = xl0.w + xr.w + ev0.w; m = m > 0.f ? m : NEG * m; s0 += m * av.w;
            m = xl1.x + xr.x + ev1.x; m = m > 0.f ? m : NEG * m; s1 = m * av.x;
            m = xl1.y + xr.y + ev1.y; m = m > 0.f ? m : NEG * m; s1 += m * av.y;
            m = xl1.z + xr.z + ev1.z; m = m > 0.f ? m : NEG * m; s1 += m * av.z;
            m = xl1.w + xr.w + ev1.w; m = m > 0.f ? m : NEG * m; s1 += m * av.w;
            s0 += __shfl_xor_sync(0xffffffffu, s0, 1);
            s0 += __shfl_xor_sync(0xffffffffu, s0, 2);
            s1 += __shfl_xor_sync(0xffffffffu, s1, 1);
            s1 += __shfl_xor_sync(0xffffffffu, s1, 2);
            float p0 = __expf(s0), p1 = __expf(s1);
            den += p0 + p1;
            acc.x += p0 * xl0.x + p1 * xl1.x;
            acc.y += p0 * xl0.y + p1 * xl1.y;
            acc.z += p0 * xl0.z + p1 * xl1.z;
            acc.w += p0 * xl0.w + p1 * xl1.w;
        }
        if (i < r1) {
            int pe0 = g_csr[i];
            float4 xl0 = *(const float4*)&g_xl[(size_t)(pe0 & 0xFFFFF) * 128 + lane * 4];
            float4 ev0 = *(const float4*)&ee[(pe0 >> 20) * 128 + lane * 4];
            float m, s0;
            m = xl0.x + xr.x + ev0.x; m = m > 0.f ? m : NEG * m; s0 = m * av.x;
            m = xl0.y + xr.y + ev0.y; m = m > 0.f ? m : NEG * m; s0 += m * av.y;
            m = xl0.z + xr.z + ev0.z; m = m > 0.f ? m : NEG * m; s0 += m * av.z;
            m = xl0.w + xr.w + ev0.w; m = m > 0.f ? m : NEG * m; s0 += m * av.w;
            s0 += __shfl_xor_sync(0xffffffffu, s0, 1);
            s0 += __shfl_xor_sync(0xffffffffu, s0, 2);
            float p0 = __expf(s0);
            den += p0;
            acc.x += p0 * xl0.x;
            acc.y += p0 * xl0.y;
            acc.z += p0 * xl0.z;
            acc.w += p0 * xl0.w;
        }
        float inv = __frcp_rn(fmaxf(den, 1e-16f));
        float4 o;
        o.x = fmaxf(acc.x * inv + bv.x, 0.f);
        o.y = fmaxf(acc.y * inv + bv.y, 0.f);
        o.z = fmaxf(acc.z * inv + bv.z, 0.f);
        o.w = fmaxf(acc.w * inv + bv.w, 0.f);
        *(float4*)&g_agg[(size_t)node * 128 + lane * 4] = o;
        ps0 += o.x; ps1 += o.y; ps2 += o.z; ps3 += o.w;
        pq0 += o.x * o.x; pq1 += o.y * o.y; pq2 += o.z * o.z; pq3 += o.w * o.w;
    }
    red[wid][lane][0] = ps0; red[wid][lane][1] = ps1;
    red[wid][lane][2] = ps2; red[wid][lane][3] = ps3;
    red[wid][lane][4] = pq0; red[wid][lane][5] = pq1;
    red[wid][lane][6] = pq2; red[wid][lane][7] = pq3;
    __syncthreads();
    int stat = t >> 7, ch = t & 127;
    int ln = ch >> 2, j = ch & 3;
    float s = 0.f;
#pragma unroll
    for (int w = 0; w < 8; w++) s += red[w][ln][stat * 4 + j];
    g_part[blockIdx.x * 256 + t] = s;
}

// ---------------- BN finalize ----------------
__global__ void k_bnr2(const float* __restrict__ gamma,
                       const float* __restrict__ beta, int n) {
    __shared__ float sh[256];
    int t = threadIdx.x;
    float s = 0.f;
#pragma unroll 4
    for (int b = 0; b < EG; b++) s += g_part[b * 256 + t];
    sh[t] = s;
    __syncthreads();
    if (t < 128) {
        float inv_n = 1.0f / (float)n;
        float mu = sh[t] * inv_n;
        float var = sh[128 + t] * inv_n - mu * mu;
        float rs = rsqrtf(var + 1e-5f);
        float sc = gamma[t] * rs;
        g_scale[t] = sc;
        g_shift[t] = beta[t] - mu * sc;
    }
}
__global__ void k_apply(int res, int n) {
    int idx = blockIdx.x * blockDim.x + threadIdx.x;
    if (idx >= n * 32) return;
    int c4 = (idx & 31) * 4;
    float4 v = *(const float4*)&g_agg[(size_t)idx * 4];
    float4 sc = *(const float4*)&g_scale[c4];
    float4 sf = *(const float4*)&g_shift[c4];
    float4 o;
    o.x = sc.x * v.x + sf.x;
    o.y = sc.y * v.y + sf.y;
    o.z = sc.z * v.z + sf.z;
    o.w = sc.w * v.w + sf.w;
    if (res) {
        float4 hprev = *(const float4*)&g_h[(size_t)idx * 4];
        o.x += hprev.x; o.y += hprev.y; o.z += hprev.z; o.w += hprev.w;
    }
    *(float4*)&g_h[(size_t)idx * 4] = o;
}

// ---------------- pooling ----------------
__global__ void k_pool_zero() {
    int i = blockIdx.x * blockDim.x + threadIdx.x;
    if (i < GNUM * HID) g_pool[i] = 0.f;
    if (i < GNUM) g_pcnt[i] = 0;
}
__global__ void k_pool(const int* __restrict__ batch, int n) {
    const int CHUNK = 256;
    int t = threadIdx.x;
    int r0 = blockIdx.x * CHUNK;
    int rend = min(r0 + CHUNK, n);
    float a = 0.f;
    int lc = 0, cur = -1;
    for (int r = r0; r < rend; r++) {
        int g = batch[r];
        if (g != cur) {
            if (cur >= 0) {
                atomicAdd(&g_pool[cur * 128 + t], a);
                if (t == 0) atomicAdd(&g_pcnt[cur], lc);
            }
            a = 0.f;
            lc = 0;
            cur = g;
        }
        a += g_h[(size_t)r * 128 + t];
        lc++;
    }
    if (cur >= 0) {
        atomicAdd(&g_pool[cur * 128 + t], a);
        if (t == 0) atomicAdd(&g_pcnt[cur], lc);
    }
}
__global__ void k_pool_fin(float* __restrict__ out) {
    int i = blockIdx.x * blockDim.x + threadIdx.x;
    if (i >= GNUM * HID) return;
    out[i] = g_pool[i] / fmaxf((float)g_pcnt[i >> 7], 1.0f);
}

// ---------------- host launch ----------------
extern "C" void kernel_launch(void* const* d_in, const int* in_sizes, int n_in,
                              void* d_out, int out_size) {
    const int* tok = (const int*)d_in[0];
    const float* bbox = (const float*)d_in[1];
    const int* ei = (const int*)d_in[2];
    const int* eattr = (const int*)d_in[3];
    const int* batch = (const int*)d_in[4];
    const float* temb = (const float*)d_in[5];
    const float* bW = (const float*)d_in[6];
    const float* bb = (const float*)d_in[7];
    const float* relemb = (const float*)d_in[8];
    const float* Wl0 = (const float*)d_in[9];
    const float* bl0 = (const float*)d_in[10];
    const float* Wr0 = (const float*)d_in[11];
    const float* br0 = (const float*)d_in[12];
    const float* We0 = (const float*)d_in[13];
    const float* att0 = (const float*)d_in[14];
    const float* bias0 = (const float*)d_in[15];
    const float* gamma0 = (const float*)d_in[16];
    const float* beta0 = (const float*)d_in[17];
    const float* WlS = (const float*)d_in[18];
    const float* blS = (const float*)d_in[19];
    const float* WrS = (const float*)d_in[20];
    const float* brS = (const float*)d_in[21];
    const float* WeS = (const float*)d_in[22];
    const float* attS = (const float*)d_in[23];
    const float* biasS = (const float*)d_in[24];
    const float* gammaS = (const float*)d_in[25];
    const float* betaS = (const float*)d_in[26];

    int n = in_sizes[0];
    int e = in_sizes[3];
    const int* src = ei;
    const int* dst = ei + e;

    float *p_x0, *p_h, *p_xl, *p_xr;
    cudaGetSymbolAddress((void**)&p_x0, g_x0);
    cudaGetSymbolAddress((void**)&p_h, g_h);
    cudaGetSymbolAddress((void**)&p_xl, g_xl);
    cudaGetSymbolAddress((void**)&p_xr, g_xr);

    int gN = (n + 255) / 256;
    int gE = (e + 255) / 256;

    k_build_x0<<<(n * 72 + 255) / 256, 256>>>(tok, bbox, temb, bW, bb, n);

    int nbScan = (n + 1023) / 1024;
    k_zero_deg<<<gN, 256>>>(n);
    k_hist<<<gE, 256>>>(dst, e);
    k_scan1<<<nbScan, 1024>>>(n);
    k_scan2<<<1, 32>>>(nbScan);
    k_scan3<<<gN, 256>>>(n);
    k_zero_deg<<<gN, 256>>>(n);
    k_scatter<<<gE, 256>>>(src, dst, eattr, e);

    int gemmGrid = (n + 63) / 64;

    for (int l = 0; l < 3; l++) {
        const float *Wl, *bl, *Wr, *br, *We, *att, *bias, *gamma, *beta;
        if (l == 0) {
            Wl = Wl0; bl = bl0; Wr = Wr0; br = br0; We = We0;
            att = att0; bias = bias0; gamma = gamma0; beta = beta0;
        } else {
            int j = l - 1;
            Wl = WlS + (size_t)j * 128 * 128; bl = blS + j * 128;
            Wr = WrS + (size_t)j * 128 * 128; br = brS + j * 128;
            We = WeS + (size_t)j * 16 * 128;
            att = attS + j * 128;
            bias = biasS + j * 128; gamma = gammaS + j * 128; beta = betaS + j * 128;
        }
        k_eetab<<<(RELN * HID + 255) / 256, 256>>>(relemb, We);
        if (l == 0) {
            k_gemm2<288><<<gemmGrid, 256>>>(p_x0, Wl, bl, Wr, br, p_xl, p_xr, n);
        } else {
            k_gemm2<128><<<gemmGrid, 256>>>(p_h, Wl, bl, Wr, br, p_xl, p_xr, n);
        }
        k_edge<<<EG, 256>>>(att, bias, n);
        k_bnr2<<<1, 256>>>(gamma, beta, n);
        k_apply<<<(n * 32 + 255) / 256, 256>>>(l > 0 ? 1 : 0, n);
    }

    k_pool_zero<<<(GNUM * HID + 255) / 256, 256>>>();
    k_pool<<<(n + 255) / 256, 128>>>(batch, n);
    k_pool_fin<<<(GNUM * HID + 255) / 256, 256>>>((float*)d_out);
}